// round 4
// baseline (speedup 1.0000x reference)
#include <cuda_runtime.h>
#include <cstdint>

// DisulfideEnergy: sulfur-pair energy scatter + fused residue reduction.
//
// Inputs (metadata order):
//   d_in[0] coords            f32  [500000, 3]
//   d_in[1] atom_description  i32  [500000, 4]  (at_name, resnum, batch, chain)
//   d_in[2] atom_pairs        i32  [4000000, 2]
//   d_in[3] alternative_mask  [500000, 4] bool->4-byte dtype; u32 nonzero==true
//   d_in[4] facc              f32  [500000]  (unused)
// Output (single f32 buffer):
//   [0 .. 64000)              resi_energy (8,4,500,4)
//   [64000 .. 2064000)        atom_energy (500000,4)
//   [2064000 .. 6064000)      sulfur      (4000000) as 0.0/1.0
//
// Key insight: resi_energy == segment_sum(atom_energy), and atom_energy is
// built from ~2.5K sulfur pairs. Each heavy pair adds `net` to both the atomE
// slots AND the resi slots directly -> no separate reduction pass needed.

#define N_CHAINS   4
#define N_RES      500
#define SG_CODE    7
#define MAX_ATOMS  500000
#define MAX_WORDS  ((MAX_ATOMS + 31) / 32)   // 15625

__device__ uint32_t g_sgmask[MAX_WORDS + 32];

// ---------------------------------------------------------------------------
// Kernel 1: build SG bitmask. 4 atoms per thread (MLP=4), ballot per chunk.
// Block of 256 threads covers 1024 consecutive atoms (32 mask words).
// ---------------------------------------------------------------------------
__global__ void mask_kernel(const int* __restrict__ desc, int n_atoms)
{
    int base = blockIdx.x * 1024;
    int an[4];
#pragma unroll
    for (int u = 0; u < 4; u++) {
        int a = base + u * 256 + threadIdx.x;
        an[u] = (a < n_atoms) ? __ldcs(desc + 4 * a) : 0;   // at_name column
    }
#pragma unroll
    for (int u = 0; u < 4; u++) {
        int a = base + u * 256 + threadIdx.x;
        unsigned ball = __ballot_sync(0xffffffffu, an[u] == SG_CODE);
        if ((threadIdx.x & 31) == 0 && a < n_atoms)
            g_sgmask[a >> 5] = ball;
    }
}

// ---------------------------------------------------------------------------
// Heavy path: only true sulfur pairs (~1/1600). Does atomE AND resi atomics.
// ---------------------------------------------------------------------------
__device__ __forceinline__ void heavy_pair(int i, int j,
                                           const float* __restrict__ coords,
                                           const int4* __restrict__ desc4,
                                           const uint32_t* __restrict__ amask,
                                           float* __restrict__ atomE,
                                           float* __restrict__ resi)
{
    float dx = __ldg(coords + 3 * i + 0) - __ldg(coords + 3 * j + 0) + 1e-6f;
    float dy = __ldg(coords + 3 * i + 1) - __ldg(coords + 3 * j + 1) + 1e-6f;
    float dz = __ldg(coords + 3 * i + 2) - __ldg(coords + 3 * j + 2) + 1e-6f;
    float dist = sqrtf(dx * dx + dy * dy + dz * dz);

    int4 di = __ldg(desc4 + i);   // (at_name, resnum, batch, chain)
    int4 dj = __ldg(desc4 + j);

    float rd  = fabsf((float)(di.y - dj.y));
    float rds = (rd > 0.f) ? rd : 1.0f;

    // -0.001*298.0 = -0.298
    float energy = -0.298f * (2.1f + 2.9823825f * logf(rds))
                 + 5.0f * fabsf(dist - 2.04f);
    float net = 0.5f * energy;

    int flat_i = (di.z * N_CHAINS + di.w) * N_RES + di.y;
    int flat_j = (dj.z * N_CHAINS + dj.w) * N_RES + dj.y;

    uint4 mi = *reinterpret_cast<const uint4*>(amask + 4 * (size_t)i);
    uint4 mj = *reinterpret_cast<const uint4*>(amask + 4 * (size_t)j);

#define ALT(A, MI, MJ)                                                       \
    if ((MI) && (MJ)) {                                                      \
        atomicAdd(atomE + 4 * (size_t)i + (A), net);                         \
        atomicAdd(atomE + 4 * (size_t)j + (A), net);                         \
        atomicAdd(resi  + 4 * (size_t)flat_i + (A), net);                    \
        atomicAdd(resi  + 4 * (size_t)flat_j + (A), net);                    \
    }
    ALT(0, mi.x, mj.x)
    ALT(1, mi.y, mj.y)
    ALT(2, mi.z, mj.z)
    ALT(3, mi.w, mj.w)
#undef ALT
}

// ---------------------------------------------------------------------------
// Kernel 2: pair sweep. SG bitmask in shared memory (62.5 KB).
// 4 pairs per thread-iteration: 2x int4 streaming load, float4 streaming store.
// ---------------------------------------------------------------------------
__global__ void pair_kernel(const int4* __restrict__ pairs2,
                            const float* __restrict__ coords,
                            const int4* __restrict__ desc4,
                            const uint32_t* __restrict__ amask,
                            float* __restrict__ out,
                            int n_pairs, int n_atoms, int resi_floats)
{
    extern __shared__ uint32_t smask[];
    int nwords = (n_atoms + 31) >> 5;
    for (int w = threadIdx.x; w < nwords; w += blockDim.x)
        smask[w] = g_sgmask[w];
    __syncthreads();

    float* resi  = out;
    float* atomE = out + resi_floats;
    float* sout  = atomE + 4 * (size_t)n_atoms;

    int n4 = n_pairs >> 2;                     // groups of 4 pairs
    int stride = gridDim.x * blockDim.x;

    for (int p = blockIdx.x * blockDim.x + threadIdx.x; p < n4; p += stride) {
        int4 pa = __ldcs(pairs2 + 2 * p);      // pairs 0,1
        int4 pb = __ldcs(pairs2 + 2 * p + 1);  // pairs 2,3

        unsigned s0 = (smask[pa.x >> 5] >> (pa.x & 31))
                    & (smask[pa.y >> 5] >> (pa.y & 31)) & 1u;
        unsigned s1 = (smask[pa.z >> 5] >> (pa.z & 31))
                    & (smask[pa.w >> 5] >> (pa.w & 31)) & 1u;
        unsigned s2 = (smask[pb.x >> 5] >> (pb.x & 31))
                    & (smask[pb.y >> 5] >> (pb.y & 31)) & 1u;
        unsigned s3 = (smask[pb.z >> 5] >> (pb.z & 31))
                    & (smask[pb.w >> 5] >> (pb.w & 31)) & 1u;

        float4 so;
        so.x = s0 ? 1.0f : 0.0f;
        so.y = s1 ? 1.0f : 0.0f;
        so.z = s2 ? 1.0f : 0.0f;
        so.w = s3 ? 1.0f : 0.0f;
        __stcs(reinterpret_cast<float4*>(sout) + p, so);

        if (s0) heavy_pair(pa.x, pa.y, coords, desc4, amask, atomE, resi);
        if (s1) heavy_pair(pa.z, pa.w, coords, desc4, amask, atomE, resi);
        if (s2) heavy_pair(pb.x, pb.y, coords, desc4, amask, atomE, resi);
        if (s3) heavy_pair(pb.z, pb.w, coords, desc4, amask, atomE, resi);
    }

    // tail: n_pairs % 4 (zero for this problem, kept general)
    if (blockIdx.x == 0 && threadIdx.x == 0) {
        const int* pp = reinterpret_cast<const int*>(pairs2);
        for (int q = n4 << 2; q < n_pairs; q++) {
            int i = pp[2 * q], j = pp[2 * q + 1];
            unsigned s = (smask[i >> 5] >> (i & 31))
                       & (smask[j >> 5] >> (j & 31)) & 1u;
            sout[q] = s ? 1.0f : 0.0f;
            if (s) heavy_pair(i, j, coords, desc4, amask, atomE, resi);
        }
    }
}

// ---------------------------------------------------------------------------
extern "C" void kernel_launch(void* const* d_in, const int* in_sizes, int n_in,
                              void* d_out, int out_size)
{
    const float*    coords = (const float*)d_in[0];
    const int*      desc   = (const int*)d_in[1];
    const int*      pairs  = (const int*)d_in[2];
    const uint32_t* amask  = (const uint32_t*)d_in[3];
    float*          out    = (float*)d_out;

    int n_atoms = in_sizes[0] / 3;
    int n_pairs = in_sizes[2] / 2;
    int n_alt   = in_sizes[3] / n_atoms;                      // 4
    int resi_floats = out_size - n_atoms * n_alt - n_pairs;   // 64000

    int nwords = (n_atoms + 31) >> 5;
    size_t smem = (size_t)nwords * 4;                         // 62500 B

    cudaFuncSetAttribute(pair_kernel,
                         cudaFuncAttributeMaxDynamicSharedMemorySize,
                         (int)smem);

    // Zero resi + atom_energy regions via driver memset (graph-capturable,
    // near-peak BW). Sulfur region is fully overwritten by pair_kernel.
    cudaMemsetAsync(out, 0,
                    (size_t)(resi_floats + n_atoms * n_alt) * sizeof(float), 0);

    // Mask build: 1024 atoms per 256-thread block, MLP=4.
    int mblocks = (n_atoms + 1023) / 1024;
    mask_kernel<<<mblocks, 256>>>(desc, n_atoms);

    // 3 CTAs/SM (smem-limited: 3 * 62.5KB < 228KB), 148 SMs
    pair_kernel<<<444, 512, smem>>>((const int4*)pairs, coords,
                                    (const int4*)desc, amask,
                                    out, n_pairs, n_atoms, resi_floats);
}